// round 1
// baseline (speedup 1.0000x reference)
#include <cuda_runtime.h>
#include <math.h>

// ---------------------------------------------------------------------------
// Vit_Spatial_Map: B=8, N=1, C=64, H=W=256, P=8 -> Np=1024, patch_dim=4096,
// DIM=256, HEADS=4, DH=64, BN=8, M=BN*Np=8192.
//
// Pipeline:
//   emb  = patches @ W_embed^T + b_embed + pos        (8192 x 256, K=4096)
//   q    = emb @ Wq_avg^T  (Wq_avg = per-head row-mean of Wq)   (8192 x 4)
//   k    = sigmoid(q @ Wk^T)                           (32 x 1024)
//   kv   = (emb @ Wv^T) * k[bn, e/64, n]               (8192 x 256, K=256)
//   out  = kv @ Wout^T + b_out, folded to image layout (8192 x 4096, K=256)
// ---------------------------------------------------------------------------

static __device__ float g_emb[8192 * 256];
static __device__ float g_kv[8192 * 256];
static __device__ float g_wqavg[4 * 256];
static __device__ float g_q[32 * 1024];
static __device__ float g_k[32 * 1024];

enum { MODE_EMBED = 0, MODE_KV = 1, MODE_OUT = 2 };

// Tiled SGEMM: C(M x N) = A(M x K) * B(N x K)^T  (both K-major / row-major).
// BM=128, BN=64, BK=32, 256 threads, 8x4 microtile per thread.
template <int MODE, int K>
__global__ __launch_bounds__(256, 2) void gemm_k(
    const float* __restrict__ Ap, const float* __restrict__ Bp,
    float* __restrict__ Cp, const float* __restrict__ bias,
    const float* __restrict__ pos)
{
    __shared__ float As[32][128];
    __shared__ float Bs[32][64];

    const int tid   = threadIdx.x;
    const int mBase = blockIdx.y * 128;
    const int nBase = blockIdx.x * 64;
    const int tmg   = tid >> 4;    // 0..15 -> 8 rows each
    const int tng   = tid & 15;    // 0..15 -> 4 cols each

    const float* A = (MODE == MODE_EMBED) ? Ap : (MODE == MODE_KV ? g_emb : g_kv);

    // A loader: thread covers 4 m (mqa*4+r) x 4 k (kqa*4+i)
    const int mqa = tid & 31;
    const int kqa = tid >> 5;      // 0..7
    // B loader (tid < 128): 4 n x 4 k
    const int nqb = tid & 15;
    const int kqb = (tid >> 4) & 7;

    float acc[8][4];
#pragma unroll
    for (int i = 0; i < 8; i++)
#pragma unroll
        for (int j = 0; j < 4; j++) acc[i][j] = 0.0f;

    for (int kt = 0; kt < K; kt += 32) {
        float4 av[4];
        float4 bv[4];
        const int ka = kt + kqa * 4;

        if (MODE == MODE_EMBED) {
            // Gather from x: k = c*64 + kh*8 + kw  (kw in {0,4}, 4 contiguous)
            const int c  = ka >> 6;
            const int kh = (ka >> 3) & 7;
            const int kw = ka & 7;
#pragma unroll
            for (int r = 0; r < 4; r++) {
                const int m  = mBase + mqa * 4 + r;
                const int bn = m >> 10, n = m & 1023;
                const int ph = n >> 5, pw = n & 31;
                const size_t idx =
                    ((((size_t)bn * 64 + c) * 256) + (size_t)(ph * 8 + kh)) * 256
                    + (size_t)(pw * 8 + kw);
                av[r] = *reinterpret_cast<const float4*>(A + idx);
            }
        } else {
#pragma unroll
            for (int r = 0; r < 4; r++)
                av[r] = *reinterpret_cast<const float4*>(
                    A + (size_t)(mBase + mqa * 4 + r) * K + ka);
        }

        if (tid < 128) {
            const int kb = kt + kqb * 4;
#pragma unroll
            for (int r = 0; r < 4; r++)
                bv[r] = *reinterpret_cast<const float4*>(
                    Bp + (size_t)(nBase + nqb * 4 + r) * K + kb);
        }

        __syncthreads();  // previous tile fully consumed

        {   // 4x4 in-register transpose -> float4 STS along M (conflict-free)
            const float* f0 = &av[0].x;
            const float* f1 = &av[1].x;
            const float* f2 = &av[2].x;
            const float* f3 = &av[3].x;
#pragma unroll
            for (int i = 0; i < 4; i++)
                *reinterpret_cast<float4*>(&As[kqa * 4 + i][mqa * 4]) =
                    make_float4(f0[i], f1[i], f2[i], f3[i]);
        }
        if (tid < 128) {
            const float* f0 = &bv[0].x;
            const float* f1 = &bv[1].x;
            const float* f2 = &bv[2].x;
            const float* f3 = &bv[3].x;
#pragma unroll
            for (int i = 0; i < 4; i++)
                *reinterpret_cast<float4*>(&Bs[kqb * 4 + i][nqb * 4]) =
                    make_float4(f0[i], f1[i], f2[i], f3[i]);
        }

        __syncthreads();

#pragma unroll
        for (int kk = 0; kk < 32; kk++) {
            const float4 a0 = *reinterpret_cast<const float4*>(&As[kk][tmg * 8]);
            const float4 a1 = *reinterpret_cast<const float4*>(&As[kk][tmg * 8 + 4]);
            const float4 b  = *reinterpret_cast<const float4*>(&Bs[kk][tng * 4]);
            const float am[8] = {a0.x, a0.y, a0.z, a0.w, a1.x, a1.y, a1.z, a1.w};
            const float bb[4] = {b.x, b.y, b.z, b.w};
#pragma unroll
            for (int i = 0; i < 8; i++)
#pragma unroll
                for (int j = 0; j < 4; j++) acc[i][j] += am[i] * bb[j];
        }
    }

    // Epilogue
    const int col0 = nBase + tng * 4;
#pragma unroll
    for (int i = 0; i < 8; i++) {
        const int m  = mBase + tmg * 8 + i;
        const int bn = m >> 10, n = m & 1023;
        float4 v = make_float4(acc[i][0], acc[i][1], acc[i][2], acc[i][3]);

        if (MODE == MODE_EMBED) {
            const float* pr = pos + (size_t)n * 256 + col0;
            v.x += bias[col0 + 0] + pr[0];
            v.y += bias[col0 + 1] + pr[1];
            v.z += bias[col0 + 2] + pr[2];
            v.w += bias[col0 + 3] + pr[3];
            *reinterpret_cast<float4*>(&g_emb[(size_t)m * 256 + col0]) = v;
        } else if (MODE == MODE_KV) {
            const float kf = g_k[(bn * 4 + (col0 >> 6)) * 1024 + n];
            v.x *= kf; v.y *= kf; v.z *= kf; v.w *= kf;
            *reinterpret_cast<float4*>(&g_kv[(size_t)m * 256 + col0]) = v;
        } else {
            v.x += bias[col0 + 0];
            v.y += bias[col0 + 1];
            v.z += bias[col0 + 2];
            v.w += bias[col0 + 3];
            const int ph = n >> 5, pw = n & 31;
            const int c  = col0 >> 6;
            const int kh = (col0 >> 3) & 7;
            const int kw = col0 & 7;
            const size_t idx =
                ((((size_t)bn * 64 + c) * 256) + (size_t)(ph * 8 + kh)) * 256
                + (size_t)(pw * 8 + kw);
            *reinterpret_cast<float4*>(Cp + idx) = v;
        }
    }
}

// Wq_avg[h][j] = mean over d of Wq[h*64+d][j]
__global__ void k_wqavg(const float* __restrict__ Wq)
{
    const int h = blockIdx.x;
    const int j = threadIdx.x;
    float s = 0.0f;
#pragma unroll 8
    for (int d = 0; d < 64; d++) s += Wq[(size_t)(h * 64 + d) * 256 + j];
    g_wqavg[h * 256 + j] = s * (1.0f / 64.0f);
}

// q[bn,h,n] = emb[m,:] . wqavg[h,:]   (one block per m, one warp per head)
__global__ __launch_bounds__(128) void k_q()
{
    const int m    = blockIdx.x;
    const int w    = threadIdx.x >> 5;
    const int lane = threadIdx.x & 31;
    const float* e  = g_emb + (size_t)m * 256;
    const float* wa = g_wqavg + w * 256;
    float s = 0.0f;
#pragma unroll
    for (int t = 0; t < 8; t++) s += e[lane + t * 32] * wa[lane + t * 32];
#pragma unroll
    for (int off = 16; off > 0; off >>= 1)
        s += __shfl_xor_sync(0xFFFFFFFFu, s, off);
    if (lane == 0) {
        const int bn = m >> 10, n = m & 1023;
        g_q[(bn * 4 + w) * 1024 + n] = s;
    }
}

// k[bh,m] = sigmoid( sum_n q[bh,n] * Wk[m,n] )   (one warp per output)
__global__ __launch_bounds__(256) void k_sig(const float* __restrict__ Wk)
{
    const int gw   = blockIdx.x * 8 + (threadIdx.x >> 5);
    const int lane = threadIdx.x & 31;
    const int bh   = gw >> 10;
    const int m    = gw & 1023;
    const float4* q4 = reinterpret_cast<const float4*>(g_q + (size_t)bh * 1024);
    const float4* w4 = reinterpret_cast<const float4*>(Wk + (size_t)m * 1024);
    float s = 0.0f;
#pragma unroll
    for (int t = 0; t < 8; t++) {
        const float4 a = q4[lane + t * 32];
        const float4 b = w4[lane + t * 32];
        s += a.x * b.x + a.y * b.y + a.z * b.z + a.w * b.w;
    }
#pragma unroll
    for (int off = 16; off > 0; off >>= 1)
        s += __shfl_xor_sync(0xFFFFFFFFu, s, off);
    if (lane == 0) g_k[bh * 1024 + m] = 1.0f / (1.0f + expf(-s));
}

extern "C" void kernel_launch(void* const* d_in, const int* in_sizes, int n_in,
                              void* d_out, int out_size)
{
    const float* x     = (const float*)d_in[0];  // (8,1,64,256,256)
    const float* Wemb  = (const float*)d_in[1];  // (256,4096)
    const float* bemb  = (const float*)d_in[2];  // (256,)
    const float* pos   = (const float*)d_in[3];  // (1,1024,256)
    const float* Wq    = (const float*)d_in[4];  // (256,256)
    const float* Wk    = (const float*)d_in[5];  // (1024,1024)
    const float* Wv    = (const float*)d_in[6];  // (256,256)
    const float* Wout  = (const float*)d_in[7];  // (4096,256)
    const float* bout  = (const float*)d_in[8];  // (4096,)
    float* out = (float*)d_out;                  // (8,1,64,256,256)

    // emb = patches @ Wemb^T + bemb + pos
    gemm_k<MODE_EMBED, 4096><<<dim3(4, 64), 256>>>(x, Wemb, nullptr, bemb, pos);
    // Wq row-average (independent of emb)
    k_wqavg<<<4, 256>>>(Wq);
    // q
    k_q<<<8192, 128>>>();
    // k = sigmoid(q @ Wk^T)
    k_sig<<<4096, 256>>>(Wk);
    // kv = (emb @ Wv^T) * k
    gemm_k<MODE_KV, 256><<<dim3(4, 64), 256>>>(nullptr, Wv, nullptr, nullptr, nullptr);
    // out = fold(kv @ Wout^T + bout)
    gemm_k<MODE_OUT, 256><<<dim3(64, 64), 256>>>(nullptr, Wout, out, bout, nullptr);
}

// round 2
// speedup vs baseline: 1.6656x; 1.6656x over previous
#include <cuda_runtime.h>
#include <math.h>
#include <stdint.h>

// ---------------------------------------------------------------------------
// Vit_Spatial_Map: B=8, N=1, C=64, H=W=256, P=8 -> Np=1024, patch_dim=4096,
// DIM=256, HEADS=4, DH=64, BN=8, M=BN*Np=8192.
//
//   emb  = patches @ W_embed^T + b_embed + pos        (8192 x 256, K=4096)
//   q    = emb @ Wq_avg^T  (Wq_avg = per-head row-mean of Wq)   (8192 x 4)
//   k    = sigmoid(q @ Wk^T)                           (32 x 1024)
//   kv   = (emb @ Wv^T) * k[bn, e/64, n]               (8192 x 256, K=256)
//   out  = kv @ Wout^T + b_out, folded to image layout (8192 x 4096, K=256)
//
// GEMMs run on tensor cores: TF32 mma.sync m16n8k8, fp32 accumulate.
// ---------------------------------------------------------------------------

static __device__ float g_emb[8192 * 256];
static __device__ float g_kv[8192 * 256];
static __device__ float g_wqavg[4 * 256];
static __device__ float g_q[32 * 1024];
static __device__ float g_k[32 * 1024];

enum { MODE_EMBED = 0, MODE_KV = 1, MODE_OUT = 2 };

__device__ __forceinline__ uint32_t f2tf32(float f) {
    uint32_t u;
    asm("cvt.rna.tf32.f32 %0, %1;" : "=r"(u) : "f"(f));
    return u;
}

__device__ __forceinline__ void mma_tf32(float* c, const uint32_t* a, const uint32_t* b) {
    asm volatile(
        "mma.sync.aligned.m16n8k8.row.col.f32.tf32.tf32.f32 "
        "{%0,%1,%2,%3}, {%4,%5,%6,%7}, {%8,%9}, {%0,%1,%2,%3};"
        : "+f"(c[0]), "+f"(c[1]), "+f"(c[2]), "+f"(c[3])
        : "r"(a[0]), "r"(a[1]), "r"(a[2]), "r"(a[3]), "r"(b[0]), "r"(b[1]));
}

// C(M x N) = A(M x K) * B(N x K)^T.  BM=128, BN=128, BK=32, 256 threads.
// Warp grid 4(m) x 2(n); warp tile 32 x 64 = (2 x m16) x (8 x n8).
template <int MODE, int K>
__global__ __launch_bounds__(256) void gemm_tf32(
    const float* __restrict__ Ap, const float* __restrict__ Bp,
    float* __restrict__ Cp, const float* __restrict__ bias,
    const float* __restrict__ pos)
{
    __shared__ uint32_t As[32][132];  // [k][m], padded
    __shared__ uint32_t Bs[32][132];  // [k][n], padded

    const int tid   = threadIdx.x;
    const int mBase = blockIdx.y * 128;
    const int nBase = blockIdx.x * 128;

    const int warp = tid >> 5;
    const int lane = tid & 31;
    const int g    = lane >> 2;   // 0..7
    const int tg   = lane & 3;    // 0..3
    const int mw   = (warp & 3) * 32;  // warp m offset in tile
    const int nw   = (warp >> 2) * 64; // warp n offset in tile

    const float* A = (MODE == MODE_EMBED) ? Ap : (MODE == MODE_KV ? g_emb : g_kv);

    // loaders: each thread stages a 4m x 4k (A) and 4n x 4k (B) sub-block
    const int mq = tid & 31;   // *4 -> 128 rows
    const int kq = tid >> 5;   // *4 -> 32 k

    float acc[2][8][4];
#pragma unroll
    for (int i = 0; i < 2; i++)
#pragma unroll
        for (int j = 0; j < 8; j++)
#pragma unroll
            for (int l = 0; l < 4; l++) acc[i][j][l] = 0.0f;

    for (int kt = 0; kt < K; kt += 32) {
        float4 av[4], bv[4];
        const int ka = kt + kq * 4;

        if (MODE == MODE_EMBED) {
            // gather from x: k = c*64 + kh*8 + kw (kw in {0,4}: float4-contiguous)
            const int c  = ka >> 6;
            const int kh = (ka >> 3) & 7;
            const int kw = ka & 7;
#pragma unroll
            for (int r = 0; r < 4; r++) {
                const int m  = mBase + mq * 4 + r;
                const int bn = m >> 10, n = m & 1023;
                const int ph = n >> 5, pw = n & 31;
                const size_t idx =
                    ((((size_t)bn * 64 + c) * 256) + (size_t)(ph * 8 + kh)) * 256
                    + (size_t)(pw * 8 + kw);
                av[r] = *reinterpret_cast<const float4*>(A + idx);
            }
        } else {
#pragma unroll
            for (int r = 0; r < 4; r++)
                av[r] = *reinterpret_cast<const float4*>(
                    A + (size_t)(mBase + mq * 4 + r) * K + ka);
        }
#pragma unroll
        for (int r = 0; r < 4; r++)
            bv[r] = *reinterpret_cast<const float4*>(
                Bp + (size_t)(nBase + mq * 4 + r) * K + ka);

        __syncthreads();  // previous tile fully consumed

        {   // 4x4 transpose in registers, convert to tf32, STS along m/n
            const float* a0 = &av[0].x;
            const float* a1 = &av[1].x;
            const float* a2 = &av[2].x;
            const float* a3 = &av[3].x;
            const float* b0 = &bv[0].x;
            const float* b1 = &bv[1].x;
            const float* b2 = &bv[2].x;
            const float* b3 = &bv[3].x;
#pragma unroll
            for (int i = 0; i < 4; i++) {
                uint4 ua = make_uint4(f2tf32(a0[i]), f2tf32(a1[i]),
                                      f2tf32(a2[i]), f2tf32(a3[i]));
                uint4 ub = make_uint4(f2tf32(b0[i]), f2tf32(b1[i]),
                                      f2tf32(b2[i]), f2tf32(b3[i]));
                *reinterpret_cast<uint4*>(&As[kq * 4 + i][mq * 4]) = ua;
                *reinterpret_cast<uint4*>(&Bs[kq * 4 + i][mq * 4]) = ub;
            }
        }

        __syncthreads();

#pragma unroll
        for (int ks = 0; ks < 4; ks++) {
            const uint32_t* A0 = &As[ks * 8 + tg][0];
            const uint32_t* A4 = &As[ks * 8 + tg + 4][0];
            const uint32_t* B0 = &Bs[ks * 8 + tg][0];
            const uint32_t* B4 = &Bs[ks * 8 + tg + 4][0];

            uint32_t a[2][4], b[8][2];
#pragma unroll
            for (int mt = 0; mt < 2; mt++) {
                const int mo = mw + mt * 16 + g;
                a[mt][0] = A0[mo];
                a[mt][1] = A0[mo + 8];
                a[mt][2] = A4[mo];
                a[mt][3] = A4[mo + 8];
            }
#pragma unroll
            for (int nt = 0; nt < 8; nt++) {
                const int no = nw + nt * 8 + g;
                b[nt][0] = B0[no];
                b[nt][1] = B4[no];
            }
#pragma unroll
            for (int mt = 0; mt < 2; mt++)
#pragma unroll
                for (int nt = 0; nt < 8; nt++)
                    mma_tf32(acc[mt][nt], a[mt], b[nt]);
        }
    }

    // ---------------- epilogue ----------------
#pragma unroll
    for (int mt = 0; mt < 2; mt++) {
#pragma unroll
        for (int half = 0; half < 2; half++) {
            const int m  = mBase + mw + mt * 16 + g + half * 8;
            const int bn = m >> 10, n = m & 1023;
            float kf;
            if (MODE == MODE_KV) {
                const int h = (nBase + nw) >> 6;  // constant per warp (nw mult of 64)
                kf = g_k[(bn * 4 + h) * 1024 + n];
            }
#pragma unroll
            for (int nt = 0; nt < 8; nt++) {
                const int col = nBase + nw + nt * 8 + tg * 2;
                float vx = acc[mt][nt][half * 2 + 0];
                float vy = acc[mt][nt][half * 2 + 1];

                if (MODE == MODE_EMBED) {
                    const float* pr = pos + (size_t)n * 256 + col;
                    vx += bias[col + 0] + pr[0];
                    vy += bias[col + 1] + pr[1];
                    *reinterpret_cast<float2*>(&g_emb[(size_t)m * 256 + col]) =
                        make_float2(vx, vy);
                } else if (MODE == MODE_KV) {
                    vx *= kf; vy *= kf;
                    *reinterpret_cast<float2*>(&g_kv[(size_t)m * 256 + col]) =
                        make_float2(vx, vy);
                } else {
                    vx += bias[col + 0];
                    vy += bias[col + 1];
                    const int ph = n >> 5, pw = n & 31;
                    const int c  = col >> 6;
                    const int kh = (col >> 3) & 7;
                    const int kw = col & 7;
                    const size_t idx =
                        ((((size_t)bn * 64 + c) * 256) + (size_t)(ph * 8 + kh)) * 256
                        + (size_t)(pw * 8 + kw);
                    *reinterpret_cast<float2*>(Cp + idx) = make_float2(vx, vy);
                }
            }
        }
    }
}

// Wq_avg[h][j] = mean over d of Wq[h*64+d][j]
__global__ void k_wqavg(const float* __restrict__ Wq)
{
    const int h = blockIdx.x;
    const int j = threadIdx.x;
    float s = 0.0f;
#pragma unroll 8
    for (int d = 0; d < 64; d++) s += Wq[(size_t)(h * 64 + d) * 256 + j];
    g_wqavg[h * 256 + j] = s * (1.0f / 64.0f);
}

// q[bn,h,n] = emb[m,:] . wqavg[h,:]
__global__ __launch_bounds__(128) void k_q()
{
    const int m    = blockIdx.x;
    const int w    = threadIdx.x >> 5;
    const int lane = threadIdx.x & 31;
    const float* e  = g_emb + (size_t)m * 256;
    const float* wa = g_wqavg + w * 256;
    float s = 0.0f;
#pragma unroll
    for (int t = 0; t < 8; t++) s += e[lane + t * 32] * wa[lane + t * 32];
#pragma unroll
    for (int off = 16; off > 0; off >>= 1)
        s += __shfl_xor_sync(0xFFFFFFFFu, s, off);
    if (lane == 0) {
        const int bn = m >> 10, n = m & 1023;
        g_q[(bn * 4 + w) * 1024 + n] = s;
    }
}

// k[bh,m] = sigmoid( sum_n q[bh,n] * Wk[m,n] )
__global__ __launch_bounds__(256) void k_sig(const float* __restrict__ Wk)
{
    const int gw   = blockIdx.x * 8 + (threadIdx.x >> 5);
    const int lane = threadIdx.x & 31;
    const int bh   = gw >> 10;
    const int m    = gw & 1023;
    const float4* q4 = reinterpret_cast<const float4*>(g_q + (size_t)bh * 1024);
    const float4* w4 = reinterpret_cast<const float4*>(Wk + (size_t)m * 1024);
    float s = 0.0f;
#pragma unroll
    for (int t = 0; t < 8; t++) {
        const float4 a = q4[lane + t * 32];
        const float4 b = w4[lane + t * 32];
        s += a.x * b.x + a.y * b.y + a.z * b.z + a.w * b.w;
    }
#pragma unroll
    for (int off = 16; off > 0; off >>= 1)
        s += __shfl_xor_sync(0xFFFFFFFFu, s, off);
    if (lane == 0) g_k[bh * 1024 + m] = 1.0f / (1.0f + expf(-s));
}

extern "C" void kernel_launch(void* const* d_in, const int* in_sizes, int n_in,
                              void* d_out, int out_size)
{
    const float* x     = (const float*)d_in[0];  // (8,1,64,256,256)
    const float* Wemb  = (const float*)d_in[1];  // (256,4096)
    const float* bemb  = (const float*)d_in[2];  // (256,)
    const float* pos   = (const float*)d_in[3];  // (1,1024,256)
    const float* Wq    = (const float*)d_in[4];  // (256,256)
    const float* Wk    = (const float*)d_in[5];  // (1024,1024)
    const float* Wv    = (const float*)d_in[6];  // (256,256)
    const float* Wout  = (const float*)d_in[7];  // (4096,256)
    const float* bout  = (const float*)d_in[8];  // (4096,)
    float* out = (float*)d_out;                  // (8,1,64,256,256)

    gemm_tf32<MODE_EMBED, 4096><<<dim3(2, 64), 256>>>(x, Wemb, nullptr, bemb, pos);
    k_wqavg<<<4, 256>>>(Wq);
    k_q<<<8192, 128>>>();
    k_sig<<<4096, 256>>>(Wk);
    gemm_tf32<MODE_KV, 256><<<dim3(2, 64), 256>>>(nullptr, Wv, nullptr, nullptr, nullptr);
    gemm_tf32<MODE_OUT, 256><<<dim3(32, 64), 256>>>(nullptr, Wout, out, bout, nullptr);
}